// round 7
// baseline (speedup 1.0000x reference)
#include <cuda_runtime.h>

#define Hh    32
#define TIN   999
#define TINP  1000   // padded stride so arrays after xs stay 16B-aligned
#define TOT   1999
#define MAXB  7      // max batches per CTA (group A: 4, group B: up to 3)

typedef unsigned long long u64;

// ---- packed f32x2 helpers (Blackwell FFMA2/FADD2 path, PTX-only) ----
__device__ __forceinline__ u64 pk2(float a, float b) {
    u64 r; asm("mov.b64 %0, {%1, %2};" : "=l"(r) : "f"(a), "f"(b)); return r;
}
__device__ __forceinline__ void upk(u64 v, float& a, float& b) {
    asm("mov.b64 {%0, %1}, %2;" : "=f"(a), "=f"(b) : "l"(v));
}
__device__ __forceinline__ void ffma2(u64& d, u64 a, u64 b) {
    asm("fma.rn.f32x2 %0, %1, %2, %0;" : "+l"(d) : "l"(a), "l"(b));
}
__device__ __forceinline__ u64 fadd2(u64 a, u64 b) {
    u64 r; asm("add.rn.f32x2 %0, %1, %2;" : "=l"(r) : "l"(a), "l"(b)); return r;
}

// ---- precise fast activations: MUFU.EX2 / MUFU.RCP (~4e-7 rel err) ----
__device__ __forceinline__ float sigm(float x) {
    float t, r;
    asm("ex2.approx.f32 %0, %1;" : "=f"(t) : "f"(x * -1.4426950408889634f));
    asm("rcp.approx.f32 %0, %1;" : "=f"(r) : "f"(1.0f + t));
    return r;
}
__device__ __forceinline__ float tanh_f(float x) {
    float t, r;
    asm("ex2.approx.f32 %0, %1;" : "=f"(t) : "f"(x * -2.8853900817779268f));
    asm("rcp.approx.f32 %0, %1;" : "=f"(r) : "f"(1.0f + t));
    return fmaf(2.0f, r, -1.0f);   // tanh(x) = 2*sigmoid(2x) - 1
}

// group-local named barrier: 128 threads (4 warps) of one gate-group
__device__ __forceinline__ void barsync(int id) {
    asm volatile("bar.sync %0, 128;" :: "r"(id) : "memory");
}

struct SmemLayout {
    float xs[MAXB][TINP];       // staged input rows (padded stride)
    float h1s[MAXB][Hh];        // layer-1 hidden
    float h2s[MAXB][Hh];        // layer-2 hidden
    float zb1[MAXB][4][Hh];     // layer-1 gate scratch
    float zb2[MAXB][4][Hh];     // layer-2 gate scratch (double-buffered vs zb1)
    float xg[MAXB];             // autoregressive feedback
};

// One gate-group's full 1999-step recurrence over NBL batches [gb, gb+NBL).
// gate = this warp's gate (0..3); warp `gate` also owns batch gb+gate's state.
template<int NBL>
__device__ __forceinline__ void run_loop(
    SmemLayout* sm, int gb, int barid, int gate, int lane,
    const u64* whh1, const u64* wih2, const u64* whh2,
    float wih1r, float bs1, float bs2, float wlin, float blin,
    float* out_row)
{
    float c1 = 0.0f, c2 = 0.0f;
    const bool own = (gate < NBL);   // warp-uniform

    // GET_X: layer-1 scalar input for batch bl; WRITE_XG: feed output back.
    #define STEP_BODY(GET_X, WRITE_XG)                                         \
    {                                                                          \
        /* ---- layer 1: z1 = W_ih1*x + W_hh1@h1 + b ---- */                   \
        _Pragma("unroll")                                                      \
        for (int b = 0; b < NBL; b++) {                                        \
            const int bl = gb + b;                                             \
            float xb = (GET_X);                                                \
            u64 a0 = 0ull, a1 = 0ull;                                          \
            const ulonglong2* hp =                                             \
                reinterpret_cast<const ulonglong2*>(sm->h1s[bl]);              \
            _Pragma("unroll")                                                  \
            for (int p = 0; p < 8; p++) {                                      \
                ulonglong2 hv = hp[p];            /* LDS.128 broadcast */      \
                ffma2(a0, hv.x, whh1[2 * p]);                                  \
                ffma2(a1, hv.y, whh1[2 * p + 1]);                              \
            }                                                                  \
            u64 aa = fadd2(a0, a1);                                            \
            float l0, l1; upk(aa, l0, l1);                                     \
            sm->zb1[bl][gate][lane] = (l0 + l1) + fmaf(wih1r, xb, bs1);        \
        }                                                                      \
        barsync(barid);                                                        \
        /* ---- cell update 1: warp `gate` owns batch gb+gate ---- */          \
        if (own) {                                                             \
            const int bo = gb + gate;                                          \
            float zi = sm->zb1[bo][0][lane], zf = sm->zb1[bo][1][lane];        \
            float zg = sm->zb1[bo][2][lane], zo = sm->zb1[bo][3][lane];        \
            c1 = fmaf(sigm(zf), c1, sigm(zi) * tanh_f(zg));                    \
            sm->h1s[bo][lane] = sigm(zo) * tanh_f(c1);                         \
        }                                                                      \
        barsync(barid);                                                        \
        /* ---- layer 2: z2 = W_ih2@h1 + W_hh2@h2 + b ---- */                  \
        _Pragma("unroll")                                                      \
        for (int b = 0; b < NBL; b++) {                                        \
            const int bl = gb + b;                                             \
            u64 a0 = 0ull, a1 = 0ull, d0 = 0ull, d1 = 0ull;                    \
            const ulonglong2* hp1 =                                            \
                reinterpret_cast<const ulonglong2*>(sm->h1s[bl]);              \
            const ulonglong2* hp2 =                                            \
                reinterpret_cast<const ulonglong2*>(sm->h2s[bl]);              \
            _Pragma("unroll")                                                  \
            for (int p = 0; p < 8; p++) {                                      \
                ulonglong2 u = hp1[p];                                         \
                ulonglong2 v = hp2[p];                                         \
                ffma2(a0, u.x, wih2[2 * p]);                                   \
                ffma2(a1, u.y, wih2[2 * p + 1]);                               \
                ffma2(d0, v.x, whh2[2 * p]);                                   \
                ffma2(d1, v.y, whh2[2 * p + 1]);                               \
            }                                                                  \
            u64 ss = fadd2(fadd2(a0, a1), fadd2(d0, d1));                      \
            float l0, l1; upk(ss, l0, l1);                                     \
            sm->zb2[bl][gate][lane] = (l0 + l1) + bs2;                         \
        }                                                                      \
        barsync(barid);                                                        \
        /* ---- cell update 2 + linear output ---- */                          \
        if (own) {                                                             \
            const int bo = gb + gate;                                          \
            float zi = sm->zb2[bo][0][lane], zf = sm->zb2[bo][1][lane];        \
            float zg = sm->zb2[bo][2][lane], zo = sm->zb2[bo][3][lane];        \
            c2 = fmaf(sigm(zf), c2, sigm(zi) * tanh_f(zg));                    \
            float h2new = sigm(zo) * tanh_f(c2);                               \
            sm->h2s[bo][lane] = h2new;                                         \
            float v = wlin * h2new;          /* out = W_lin @ h2 + b_lin */    \
            _Pragma("unroll")                                                  \
            for (int off = 16; off; off >>= 1)                                 \
                v += __shfl_xor_sync(0xffffffffu, v, off);                     \
            if (lane == 0) {                                                   \
                float o = v + blin;                                            \
                out_row[s] = o;                                                \
                if (WRITE_XG) sm->xg[bo] = o;  /* autoregressive feedback */   \
            }                                                                  \
        }                                                                      \
    }

    // Teacher-forced phase, steps [0, TIN-1): 3 barriers/step, no xg write.
    // Hazard walk (re-verified): zb1 read(s, post-bar1) vs write(s+1) split by
    // bar2+bar3 of s; zb2 read(s, post-bar3) vs write(s+1, post-bar2) split by
    // bar1+bar2 of s+1 via reader program order; h1s/h2s RAW/WAR all >=1
    // barrier apart. The 4th barrier exists only to order the xg RAW in the
    // generative phase.
    for (int s = 0; s < TIN - 1; s++) {
        STEP_BODY(sm->xs[bl][s], false)
    }
    // Boundary step s = TIN-1: last teacher input, first xg write.
    {
        const int s = TIN - 1;
        STEP_BODY(sm->xs[bl][s], true)
    }
    // Generative phase, steps [TIN, TOT): 4 barriers/step (leading barrier
    // orders xg write at step s before its read at step s+1).
    for (int s = TIN; s < TOT; s++) {
        barsync(barid);
        STEP_BODY(sm->xg[bl], true)
    }
    #undef STEP_BODY
}

__global__ void __launch_bounds__(256, 1)
lstm_seq_kernel(const float* __restrict__ input,
                const float* __restrict__ W_ih1, const float* __restrict__ W_hh1,
                const float* __restrict__ b_ih1, const float* __restrict__ b_hh1,
                const float* __restrict__ W_ih2, const float* __restrict__ W_hh2,
                const float* __restrict__ b_ih2, const float* __restrict__ b_hh2,
                const float* __restrict__ W_lin, const float* __restrict__ b_lin,
                float* __restrict__ out)
{
    __shared__ __align__(16) SmemLayout sm;

    const int tid   = threadIdx.x;
    const int wid   = tid >> 5;
    const int lane  = tid & 31;
    const int group = wid >> 2;        // 0: batches [0,4), 1: batches [4,4+nbB)
    const int gate  = wid & 3;         // gate row group (i,f,g,o)
    const int row   = gate * Hh + lane;

    // Balanced batch partition: 136 CTAs x 7 + 12 CTAs x 6 = 1024.
    const int bid      = blockIdx.x;
    const int cta_base = (bid < 136) ? bid * 7 : 952 + (bid - 136) * 6;
    const int nb_cta   = (bid < 136) ? 7 : 6;
    const int nbB      = nb_cta - 4;   // group B batch count: 3 or 2

    // ---- register-resident weights, packed as consecutive-k f32x2 pairs ----
    u64 whh1[16], wih2[16], whh2[16];
    {
        const float2* W1  = reinterpret_cast<const float2*>(W_hh1);
        const float2* W2i = reinterpret_cast<const float2*>(W_ih2);
        const float2* W2h = reinterpret_cast<const float2*>(W_hh2);
        #pragma unroll
        for (int p = 0; p < 16; p++) {
            float2 a = __ldg(W1  + row * 16 + p); whh1[p] = pk2(a.x, a.y);
            float2 c = __ldg(W2i + row * 16 + p); wih2[p] = pk2(c.x, c.y);
            float2 d = __ldg(W2h + row * 16 + p); whh2[p] = pk2(d.x, d.y);
        }
    }
    const float wih1r = __ldg(W_ih1 + row);                      // [4H,1]
    const float bs1   = __ldg(b_ih1 + row) + __ldg(b_hh1 + row);
    const float bs2   = __ldg(b_ih2 + row) + __ldg(b_hh2 + row);
    const float wlin  = __ldg(W_lin + lane);
    const float blin  = __ldg(b_lin);

    // ---- stage input rows (warp w loads batch row w, coalesced) ----
    if (wid < nb_cta) {
        const float* src = input + (long)(cta_base + wid) * TIN;
        for (int k = lane; k < TIN; k += 32) sm.xs[wid][k] = src[k];
    }
    if (tid < MAXB * Hh) {
        (&sm.h1s[0][0])[tid] = 0.0f;
        (&sm.h2s[0][0])[tid] = 0.0f;
    }
    __syncthreads();   // one block-wide barrier before the group-local loops

    const int gb    = (group == 0) ? 0 : 4;
    const int barid = group + 1;
    const int nbl   = (group == 0) ? 4 : nbB;
    float* out_row  = (gate < nbl)
                    ? out + (long)(cta_base + gb + gate) * TOT
                    : out;   // unused (guarded by `own`), keep valid

    if (group == 0) {
        run_loop<4>(&sm, gb, barid, gate, lane, whh1, wih2, whh2,
                    wih1r, bs1, bs2, wlin, blin, out_row);
    } else if (nbB == 3) {
        run_loop<3>(&sm, gb, barid, gate, lane, whh1, wih2, whh2,
                    wih1r, bs1, bs2, wlin, blin, out_row);
    } else {
        run_loop<2>(&sm, gb, barid, gate, lane, whh1, wih2, whh2,
                    wih1r, bs1, bs2, wlin, blin, out_row);
    }
}

extern "C" void kernel_launch(void* const* d_in, const int* in_sizes, int n_in,
                              void* d_out, int out_size)
{
    (void)in_sizes; (void)n_in; (void)out_size;
    const float* input = (const float*)d_in[0];
    const float* W_ih1 = (const float*)d_in[1];
    const float* W_hh1 = (const float*)d_in[2];
    const float* b_ih1 = (const float*)d_in[3];
    const float* b_hh1 = (const float*)d_in[4];
    const float* W_ih2 = (const float*)d_in[5];
    const float* W_hh2 = (const float*)d_in[6];
    const float* b_ih2 = (const float*)d_in[7];
    const float* b_hh2 = (const float*)d_in[8];
    const float* W_lin = (const float*)d_in[9];
    const float* b_lin = (const float*)d_in[10];
    // d_in[11] = future (fixed at 1000 by the problem definition)

    dim3 grid(148);    // 1 CTA per SM (safe on 148- or 152-SM parts)
    dim3 block(256);   // 2 gate-groups x 4 warps
    lstm_seq_kernel<<<grid, block>>>(input, W_ih1, W_hh1, b_ih1, b_hh1,
                                     W_ih2, W_hh2, b_ih2, b_hh2,
                                     W_lin, b_lin, (float*)d_out);
}

// round 14
// speedup vs baseline: 1.0135x; 1.0135x over previous
#include <cuda_runtime.h>

#define Hh    32
#define TIN   999
#define TINP  1000   // padded stride so arrays after xs stay 16B-aligned
#define TOT   1999
#define MAXB  7      // max batches per CTA

typedef unsigned long long u64;

// ---- packed f32x2 helpers (Blackwell FFMA2/FADD2 path, PTX-only) ----
__device__ __forceinline__ u64 pk2(float a, float b) {
    u64 r; asm("mov.b64 %0, {%1, %2};" : "=l"(r) : "f"(a), "f"(b)); return r;
}
__device__ __forceinline__ void upk(u64 v, float& a, float& b) {
    asm("mov.b64 {%0, %1}, %2;" : "=f"(a), "=f"(b) : "l"(v));
}
__device__ __forceinline__ void ffma2(u64& d, u64 a, u64 b) {
    asm("fma.rn.f32x2 %0, %1, %2, %0;" : "+l"(d) : "l"(a), "l"(b));
}
__device__ __forceinline__ u64 fadd2(u64 a, u64 b) {
    u64 r; asm("add.rn.f32x2 %0, %1, %2;" : "=l"(r) : "l"(a), "l"(b)); return r;
}

// ---- precise fast activations: MUFU.EX2 / MUFU.RCP (~4e-7 rel err) ----
__device__ __forceinline__ float sigm(float x) {
    float t, r;
    asm("ex2.approx.f32 %0, %1;" : "=f"(t) : "f"(x * -1.4426950408889634f));
    asm("rcp.approx.f32 %0, %1;" : "=f"(r) : "f"(1.0f + t));
    return r;
}
__device__ __forceinline__ float tanh_f(float x) {
    float t, r;
    asm("ex2.approx.f32 %0, %1;" : "=f"(t) : "f"(x * -2.8853900817779268f));
    asm("rcp.approx.f32 %0, %1;" : "=f"(r) : "f"(1.0f + t));
    return fmaf(2.0f, r, -1.0f);   // tanh(x) = 2*sigmoid(2x) - 1
}

// group-local named barrier: 128 threads (4 warps) of one gate-group
__device__ __forceinline__ void barsync(int id) {
    asm volatile("bar.sync %0, 128;" :: "r"(id) : "memory");
}

struct SmemLayout {
    float xs[MAXB][TINP];       // staged input rows (padded stride)
    float h1s[MAXB][Hh];        // layer-1 hidden
    float h2s[MAXB][Hh];        // layer-2 hidden
    float zb1[MAXB][4][Hh];     // layer-1 gate scratch
    float zb2[MAXB][4][Hh];     // layer-2 gate scratch (double-buffered vs zb1)
    float xg[MAXB];             // autoregressive feedback
};

// One gate-group's full 1999-step recurrence over NBL batches [gb, gb+NBL).
// gate = this warp's gate (0..3); warp `gate` also owns batch gb+gate's state.
// Phases: A: z1 matvec | bar | B: Whh2@h2 (regs) + cell1 | bar |
//         C: Wih2@h1 + partial -> zb2 | bar | D: cell2 + output.
template<int NBL>
__device__ __forceinline__ void run_loop(
    SmemLayout* sm, int gb, int barid, int gate, int lane,
    const u64* whh1, const u64* wih2, const u64* whh2,
    float wih1r, float bs1, float bs2, float wlin, float blin,
    float* out_row)
{
    float c1 = 0.0f, c2 = 0.0f;
    const bool own = (gate < NBL);   // warp-uniform

    #define STEP_BODY(GET_X, WRITE_XG)                                         \
    {                                                                          \
        /* ---- phase A: z1 = W_ih1*x + W_hh1@h1_old + b ---- */               \
        _Pragma("unroll")                                                      \
        for (int b = 0; b < NBL; b++) {                                        \
            const int bl = gb + b;                                             \
            float xb = (GET_X);                                                \
            u64 a0 = 0ull, a1 = 0ull;                                          \
            const ulonglong2* hp =                                             \
                reinterpret_cast<const ulonglong2*>(sm->h1s[bl]);              \
            _Pragma("unroll")                                                  \
            for (int p = 0; p < 8; p++) {                                      \
                ulonglong2 hv = hp[p];            /* LDS.128 broadcast */      \
                ffma2(a0, hv.x, whh1[2 * p]);                                  \
                ffma2(a1, hv.y, whh1[2 * p + 1]);                              \
            }                                                                  \
            u64 aa = fadd2(a0, a1);                                            \
            float l0, l1; upk(aa, l0, l1);                                     \
            sm->zb1[bl][gate][lane] = (l0 + l1) + fmaf(wih1r, xb, bs1);        \
        }                                                                      \
        barsync(barid);                                                        \
        /* ---- phase B: Whh2@h2_old partial (regs) + cell1 for own batch ---- */ \
        u64 p0[NBL], p1[NBL];                                                  \
        _Pragma("unroll")                                                      \
        for (int b = 0; b < NBL; b++) {                                        \
            const int bl = gb + b;                                             \
            u64 d0 = 0ull, d1 = 0ull;                                          \
            const ulonglong2* hp2 =                                            \
                reinterpret_cast<const ulonglong2*>(sm->h2s[bl]);              \
            _Pragma("unroll")                                                  \
            for (int p = 0; p < 8; p++) {                                      \
                ulonglong2 v = hp2[p];                                         \
                ffma2(d0, v.x, whh2[2 * p]);                                   \
                ffma2(d1, v.y, whh2[2 * p + 1]);                               \
            }                                                                  \
            p0[b] = d0; p1[b] = d1;                                            \
        }                                                                      \
        if (own) {                                                             \
            const int bo = gb + gate;                                          \
            float zi = sm->zb1[bo][0][lane], zf = sm->zb1[bo][1][lane];        \
            float zg = sm->zb1[bo][2][lane], zo = sm->zb1[bo][3][lane];        \
            c1 = fmaf(sigm(zf), c1, sigm(zi) * tanh_f(zg));                    \
            sm->h1s[bo][lane] = sigm(zo) * tanh_f(c1);                         \
        }                                                                      \
        barsync(barid);                                                        \
        /* ---- phase C: z2 = Wih2@h1_new + partial + b ---- */                \
        _Pragma("unroll")                                                      \
        for (int b = 0; b < NBL; b++) {                                        \
            const int bl = gb + b;                                             \
            u64 a0 = 0ull, a1 = 0ull;                                          \
            const ulonglong2* hp1 =                                            \
                reinterpret_cast<const ulonglong2*>(sm->h1s[bl]);              \
            _Pragma("unroll")                                                  \
            for (int p = 0; p < 8; p++) {                                      \
                ulonglong2 u = hp1[p];                                         \
                ffma2(a0, u.x, wih2[2 * p]);                                   \
                ffma2(a1, u.y, wih2[2 * p + 1]);                               \
            }                                                                  \
            u64 ss = fadd2(fadd2(a0, a1), fadd2(p0[b], p1[b]));                \
            float l0, l1; upk(ss, l0, l1);                                     \
            sm->zb2[bl][gate][lane] = (l0 + l1) + bs2;                         \
        }                                                                      \
        barsync(barid);                                                        \
        /* ---- phase D: cell2 + linear output for own batch ---- */           \
        if (own) {                                                             \
            const int bo = gb + gate;                                          \
            float zi = sm->zb2[bo][0][lane], zf = sm->zb2[bo][1][lane];        \
            float zg = sm->zb2[bo][2][lane], zo = sm->zb2[bo][3][lane];        \
            c2 = fmaf(sigm(zf), c2, sigm(zi) * tanh_f(zg));                    \
            float h2new = sigm(zo) * tanh_f(c2);                               \
            sm->h2s[bo][lane] = h2new;                                         \
            float v = wlin * h2new;          /* out = W_lin @ h2 + b_lin */    \
            _Pragma("unroll")                                                  \
            for (int off = 16; off; off >>= 1)                                 \
                v += __shfl_xor_sync(0xffffffffu, v, off);                     \
            if (lane == 0) {                                                   \
                float o = v + blin;                                            \
                out_row[s] = o;                                                \
                if (WRITE_XG) sm->xg[bo] = o;  /* autoregressive feedback */   \
            }                                                                  \
        }                                                                      \
    }

    // Teacher phase, 3 barriers/step. Hazards: h1s write B(s) vs read C(s):
    // bar2; vs read A(s+1): bar3. h2s read B(s) (old) vs write D(s): bar2+3;
    // write D(s) vs read B(s+1): bar1(s+1). zb1 write A / read B: bar1; WAR
    // read B(s) vs write A(s+1): bar2+3. zb2 write C / read D: bar3; WAR read
    // D(s) vs write C(s+1): bar1+2 of s+1 (reader program order). xg needs the
    // generative-phase leading barrier only.
    for (int s = 0; s < TIN - 1; s++) {
        STEP_BODY(sm->xs[bl][s], false)
    }
    // Boundary step s = TIN-1: last teacher input, first xg write.
    {
        const int s = TIN - 1;
        STEP_BODY(sm->xs[bl][s], true)
    }
    // Generative phase: leading barrier orders xg write(s) before read(s+1).
    for (int s = TIN; s < TOT; s++) {
        barsync(barid);
        STEP_BODY(sm->xg[bl], true)
    }
    #undef STEP_BODY
}

__global__ void __launch_bounds__(384, 1)
lstm_seq_kernel(const float* __restrict__ input,
                const float* __restrict__ W_ih1, const float* __restrict__ W_hh1,
                const float* __restrict__ b_ih1, const float* __restrict__ b_hh1,
                const float* __restrict__ W_ih2, const float* __restrict__ W_hh2,
                const float* __restrict__ b_ih2, const float* __restrict__ b_hh2,
                const float* __restrict__ W_lin, const float* __restrict__ b_lin,
                float* __restrict__ out)
{
    __shared__ __align__(16) SmemLayout sm;

    const int tid   = threadIdx.x;
    const int wid   = tid >> 5;
    const int lane  = tid & 31;
    const int group = wid >> 2;        // 0,1,2
    const int gate  = wid & 3;         // gate row group (i,f,g,o)
    const int row   = gate * Hh + lane;

    // Balanced batch partition: 136 CTAs x 7 + 12 CTAs x 6 = 1024.
    const int bid      = blockIdx.x;
    const int cta_base = (bid < 136) ? bid * 7 : 952 + (bid - 136) * 6;
    const int nb_cta   = (bid < 136) ? 7 : 6;

    // ---- register-resident weights, packed as consecutive-k f32x2 pairs ----
    u64 whh1[16], wih2[16], whh2[16];
    {
        const float2* W1  = reinterpret_cast<const float2*>(W_hh1);
        const float2* W2i = reinterpret_cast<const float2*>(W_ih2);
        const float2* W2h = reinterpret_cast<const float2*>(W_hh2);
        #pragma unroll
        for (int p = 0; p < 16; p++) {
            float2 a = __ldg(W1  + row * 16 + p); whh1[p] = pk2(a.x, a.y);
            float2 c = __ldg(W2i + row * 16 + p); wih2[p] = pk2(c.x, c.y);
            float2 d = __ldg(W2h + row * 16 + p); whh2[p] = pk2(d.x, d.y);
        }
    }
    const float wih1r = __ldg(W_ih1 + row);                      // [4H,1]
    const float bs1   = __ldg(b_ih1 + row) + __ldg(b_hh1 + row);
    const float bs2   = __ldg(b_ih2 + row) + __ldg(b_hh2 + row);
    const float wlin  = __ldg(W_lin + lane);
    const float blin  = __ldg(b_lin);

    // ---- stage input rows (warp w loads batch row w, coalesced) ----
    if (wid < nb_cta) {
        const float* src = input + (long)(cta_base + wid) * TIN;
        for (int k = lane; k < TIN; k += 32) sm.xs[wid][k] = src[k];
    }
    if (tid < MAXB * Hh) {
        (&sm.h1s[0][0])[tid] = 0.0f;
        (&sm.h2s[0][0])[tid] = 0.0f;
    }
    __syncthreads();   // one block-wide barrier before the group-local loops

    // Groups: g0 -> 3 batches at +0, g1 -> 2 at +3, g2 -> (nb_cta-5) at +5.
    const int gb    = (group == 0) ? 0 : (group == 1 ? 3 : 5);
    const int nbl   = (group == 0) ? 3 : (group == 1 ? 2 : nb_cta - 5);
    const int barid = group + 1;
    float* out_row  = (gate < nbl)
                    ? out + (long)(cta_base + gb + gate) * TOT
                    : out;   // unused (guarded by `own`), keep valid

    if (group == 0) {
        run_loop<3>(&sm, gb, barid, gate, lane, whh1, wih2, whh2,
                    wih1r, bs1, bs2, wlin, blin, out_row);
    } else if (group == 1) {
        run_loop<2>(&sm, gb, barid, gate, lane, whh1, wih2, whh2,
                    wih1r, bs1, bs2, wlin, blin, out_row);
    } else if (nbl == 2) {
        run_loop<2>(&sm, gb, barid, gate, lane, whh1, wih2, whh2,
                    wih1r, bs1, bs2, wlin, blin, out_row);
    } else {
        run_loop<1>(&sm, gb, barid, gate, lane, whh1, wih2, whh2,
                    wih1r, bs1, bs2, wlin, blin, out_row);
    }
}

extern "C" void kernel_launch(void* const* d_in, const int* in_sizes, int n_in,
                              void* d_out, int out_size)
{
    (void)in_sizes; (void)n_in; (void)out_size;
    const float* input = (const float*)d_in[0];
    const float* W_ih1 = (const float*)d_in[1];
    const float* W_hh1 = (const float*)d_in[2];
    const float* b_ih1 = (const float*)d_in[3];
    const float* b_hh1 = (const float*)d_in[4];
    const float* W_ih2 = (const float*)d_in[5];
    const float* W_hh2 = (const float*)d_in[6];
    const float* b_ih2 = (const float*)d_in[7];
    const float* b_hh2 = (const float*)d_in[8];
    const float* W_lin = (const float*)d_in[9];
    const float* b_lin = (const float*)d_in[10];
    // d_in[11] = future (fixed at 1000 by the problem definition)

    dim3 grid(148);    // 1 CTA per SM
    dim3 block(384);   // 3 gate-groups x 4 warps = 12 warps/SM
    lstm_seq_kernel<<<grid, block>>>(input, W_ih1, W_hh1, b_ih1, b_hh1,
                                     W_ih2, W_hh2, b_ih2, b_hh2,
                                     W_lin, b_lin, (float*)d_out);
}

// round 15
// speedup vs baseline: 1.1301x; 1.1150x over previous
#include <cuda_runtime.h>

#define Hh    32
#define TIN   999
#define TINP  1000   // padded stride so arrays after xs stay 16B-aligned
#define TOT   1999
#define MAXB  7      // max batches per CTA

typedef unsigned long long u64;

// ---- packed f32x2 helpers (Blackwell FFMA2/FADD2 path, PTX-only) ----
__device__ __forceinline__ u64 pk2(float a, float b) {
    u64 r; asm("mov.b64 %0, {%1, %2};" : "=l"(r) : "f"(a), "f"(b)); return r;
}
__device__ __forceinline__ void upk(u64 v, float& a, float& b) {
    asm("mov.b64 {%0, %1}, %2;" : "=f"(a), "=f"(b) : "l"(v));
}
__device__ __forceinline__ void ffma2(u64& d, u64 a, u64 b) {
    asm("fma.rn.f32x2 %0, %1, %2, %0;" : "+l"(d) : "l"(a), "l"(b));
}
__device__ __forceinline__ u64 fadd2(u64 a, u64 b) {
    u64 r; asm("add.rn.f32x2 %0, %1, %2;" : "=l"(r) : "l"(a), "l"(b)); return r;
}

// ---- precise fast activations: MUFU.EX2 / MUFU.RCP (~4e-7 rel err) ----
__device__ __forceinline__ float sigm(float x) {
    float t, r;
    asm("ex2.approx.f32 %0, %1;" : "=f"(t) : "f"(x * -1.4426950408889634f));
    asm("rcp.approx.f32 %0, %1;" : "=f"(r) : "f"(1.0f + t));
    return r;
}
__device__ __forceinline__ float tanh_f(float x) {
    float t, r;
    asm("ex2.approx.f32 %0, %1;" : "=f"(t) : "f"(x * -2.8853900817779268f));
    asm("rcp.approx.f32 %0, %1;" : "=f"(r) : "f"(1.0f + t));
    return fmaf(2.0f, r, -1.0f);   // tanh(x) = 2*sigmoid(2x) - 1
}

// group-local named barrier: 128 threads (4 warps) of one gate-group
__device__ __forceinline__ void barsync(int id) {
    asm volatile("bar.sync %0, 128;" :: "r"(id) : "memory");
}

struct SmemLayout {
    float xs[MAXB][TINP];       // staged input rows (padded stride)
    float h1s[MAXB][Hh];        // layer-1 hidden
    float h2s[MAXB][Hh];        // layer-2 hidden
    float zb1[MAXB][4][Hh];     // layer-1 gate scratch
    float zb2[MAXB][4][Hh];     // layer-2 gate scratch
    float xg[MAXB];             // autoregressive feedback
};

template<int NBL>
__device__ __forceinline__ void run_loop(
    SmemLayout* sm, int gb, int barid, int gate, int lane,
    const u64* whh1, const u64* wih2, const u64* whh2,
    float wih1r, float bs1, float bs2, float wlin, float blin,
    float* out_row)
{
    float c1 = 0.0f, c2 = 0.0f;
    const bool own = (gate < NBL);   // warp-uniform

    // ================= teacher phase: 2-phase X/Y software pipeline ========
    // X(s): C(s) [Wih2@h1(s)] + B(s) [Whh2@h2(s-1)] + A(s+1) [Whh1@h1(s)+x]
    //       -> zb2(s), zb1(s+1). h1(s) loaded ONCE, feeds C and A.
    // Y(s): cell2(s)->h2(s)+out(s); cell1(s+1)->h1(s+1). 2 barriers/step.
    // Hazards: zb* write X(s)/read Y(s): bar; Y(s) read / X(s+1) write: Y-bar.
    // h1s write Y(s)/read X(s+1): bar; read X(s) pre-bar vs write Y(s): bar.
    // h2s symmetric.

    // ---- prologue: A(0) (h1 = 0, so z1 = wih1*x0 + b), then cell1(0) ----
    #pragma unroll
    for (int b = 0; b < NBL; b++) {
        const int bl = gb + b;
        sm->zb1[bl][gate][lane] = fmaf(wih1r, sm->xs[bl][0], bs1);
    }
    barsync(barid);
    if (own) {
        const int bo = gb + gate;
        float zi = sm->zb1[bo][0][lane], zf = sm->zb1[bo][1][lane];
        float zg = sm->zb1[bo][2][lane], zo = sm->zb1[bo][3][lane];
        c1 = fmaf(sigm(zf), c1, sigm(zi) * tanh_f(zg));
        sm->h1s[bo][lane] = sigm(zo) * tanh_f(c1);
    }
    barsync(barid);

    // ---- steady state: s = 0 .. TIN-2 ----
    for (int s = 0; s < TIN - 1; s++) {
        // phase X
        #pragma unroll
        for (int b = 0; b < NBL; b++) {
            const int bl = gb + b;
            u64 aA0 = 0ull, aA1 = 0ull, aC0 = 0ull, aC1 = 0ull;
            u64 aB0 = 0ull, aB1 = 0ull;
            const ulonglong2* hp1 =
                reinterpret_cast<const ulonglong2*>(sm->h1s[bl]);
            const ulonglong2* hp2 =
                reinterpret_cast<const ulonglong2*>(sm->h2s[bl]);
            #pragma unroll
            for (int p = 0; p < 8; p++) {
                ulonglong2 hv = hp1[p];            // h1(s): shared by A and C
                ffma2(aA0, hv.x, whh1[2 * p]);
                ffma2(aA1, hv.y, whh1[2 * p + 1]);
                ffma2(aC0, hv.x, wih2[2 * p]);
                ffma2(aC1, hv.y, wih2[2 * p + 1]);
                ulonglong2 wv = hp2[p];            // h2(s-1)
                ffma2(aB0, wv.x, whh2[2 * p]);
                ffma2(aB1, wv.y, whh2[2 * p + 1]);
            }
            {
                u64 aa = fadd2(aA0, aA1);
                float l0, l1; upk(aa, l0, l1);
                sm->zb1[bl][gate][lane] =
                    (l0 + l1) + fmaf(wih1r, sm->xs[bl][s + 1], bs1);
            }
            {
                u64 ss2 = fadd2(fadd2(aC0, aB0), fadd2(aC1, aB1));
                float l0, l1; upk(ss2, l0, l1);
                sm->zb2[bl][gate][lane] = (l0 + l1) + bs2;
            }
        }
        barsync(barid);
        // phase Y
        if (own) {
            const int bo = gb + gate;
            {   // cell2(s) + output(s)
                float zi = sm->zb2[bo][0][lane], zf = sm->zb2[bo][1][lane];
                float zg = sm->zb2[bo][2][lane], zo = sm->zb2[bo][3][lane];
                c2 = fmaf(sigm(zf), c2, sigm(zi) * tanh_f(zg));
                float h2new = sigm(zo) * tanh_f(c2);
                sm->h2s[bo][lane] = h2new;
                float v = wlin * h2new;
                #pragma unroll
                for (int off = 16; off; off >>= 1)
                    v += __shfl_xor_sync(0xffffffffu, v, off);
                if (lane == 0) out_row[s] = v + blin;
            }
            {   // cell1(s+1)
                float zi = sm->zb1[bo][0][lane], zf = sm->zb1[bo][1][lane];
                float zg = sm->zb1[bo][2][lane], zo = sm->zb1[bo][3][lane];
                c1 = fmaf(sigm(zf), c1, sigm(zi) * tanh_f(zg));
                sm->h1s[bo][lane] = sigm(zo) * tanh_f(c1);
            }
        }
        barsync(barid);
    }

    // ---- teacher tail: step TIN-1 (C+B -> cell2 -> out + first xg) ----
    {
        const int s = TIN - 1;
        #pragma unroll
        for (int b = 0; b < NBL; b++) {
            const int bl = gb + b;
            u64 aC0 = 0ull, aC1 = 0ull, aB0 = 0ull, aB1 = 0ull;
            const ulonglong2* hp1 =
                reinterpret_cast<const ulonglong2*>(sm->h1s[bl]);
            const ulonglong2* hp2 =
                reinterpret_cast<const ulonglong2*>(sm->h2s[bl]);
            #pragma unroll
            for (int p = 0; p < 8; p++) {
                ulonglong2 hv = hp1[p];
                ffma2(aC0, hv.x, wih2[2 * p]);
                ffma2(aC1, hv.y, wih2[2 * p + 1]);
                ulonglong2 wv = hp2[p];
                ffma2(aB0, wv.x, whh2[2 * p]);
                ffma2(aB1, wv.y, whh2[2 * p + 1]);
            }
            u64 ss2 = fadd2(fadd2(aC0, aB0), fadd2(aC1, aB1));
            float l0, l1; upk(ss2, l0, l1);
            sm->zb2[bl][gate][lane] = (l0 + l1) + bs2;
        }
        barsync(barid);
        if (own) {
            const int bo = gb + gate;
            float zi = sm->zb2[bo][0][lane], zf = sm->zb2[bo][1][lane];
            float zg = sm->zb2[bo][2][lane], zo = sm->zb2[bo][3][lane];
            c2 = fmaf(sigm(zf), c2, sigm(zi) * tanh_f(zg));
            float h2new = sigm(zo) * tanh_f(c2);
            sm->h2s[bo][lane] = h2new;
            float v = wlin * h2new;
            #pragma unroll
            for (int off = 16; off; off >>= 1)
                v += __shfl_xor_sync(0xffffffffu, v, off);
            if (lane == 0) {
                float o = v + blin;
                out_row[s] = o;
                sm->xg[bo] = o;
            }
        }
        barsync(barid);
    }

    // ================= generative phase: verified 4-phase body =============
    // A(s) reads xg (o(s-1)); leading barrier orders D(s-1) write -> A(s) read.
    for (int s = TIN; s < TOT; s++) {
        // phase A: z1 = wih1*xg + Whh1@h1(s-1) + b
        #pragma unroll
        for (int b = 0; b < NBL; b++) {
            const int bl = gb + b;
            float xb = sm->xg[bl];
            u64 a0 = 0ull, a1 = 0ull;
            const ulonglong2* hp =
                reinterpret_cast<const ulonglong2*>(sm->h1s[bl]);
            #pragma unroll
            for (int p = 0; p < 8; p++) {
                ulonglong2 hv = hp[p];
                ffma2(a0, hv.x, whh1[2 * p]);
                ffma2(a1, hv.y, whh1[2 * p + 1]);
            }
            u64 aa = fadd2(a0, a1);
            float l0, l1; upk(aa, l0, l1);
            sm->zb1[bl][gate][lane] = (l0 + l1) + fmaf(wih1r, xb, bs1);
        }
        barsync(barid);
        // phase B: Whh2@h2(s-1) partials (regs) + cell1(s)
        u64 p0[NBL], p1[NBL];
        #pragma unroll
        for (int b = 0; b < NBL; b++) {
            const int bl = gb + b;
            u64 d0 = 0ull, d1 = 0ull;
            const ulonglong2* hp2 =
                reinterpret_cast<const ulonglong2*>(sm->h2s[bl]);
            #pragma unroll
            for (int p = 0; p < 8; p++) {
                ulonglong2 v = hp2[p];
                ffma2(d0, v.x, whh2[2 * p]);
                ffma2(d1, v.y, whh2[2 * p + 1]);
            }
            p0[b] = d0; p1[b] = d1;
        }
        if (own) {
            const int bo = gb + gate;
            float zi = sm->zb1[bo][0][lane], zf = sm->zb1[bo][1][lane];
            float zg = sm->zb1[bo][2][lane], zo = sm->zb1[bo][3][lane];
            c1 = fmaf(sigm(zf), c1, sigm(zi) * tanh_f(zg));
            sm->h1s[bo][lane] = sigm(zo) * tanh_f(c1);
        }
        barsync(barid);
        // phase C: z2 = Wih2@h1(s) + partial + b
        #pragma unroll
        for (int b = 0; b < NBL; b++) {
            const int bl = gb + b;
            u64 a0 = 0ull, a1 = 0ull;
            const ulonglong2* hp1 =
                reinterpret_cast<const ulonglong2*>(sm->h1s[bl]);
            #pragma unroll
            for (int p = 0; p < 8; p++) {
                ulonglong2 u = hp1[p];
                ffma2(a0, u.x, wih2[2 * p]);
                ffma2(a1, u.y, wih2[2 * p + 1]);
            }
            u64 ss2 = fadd2(fadd2(a0, a1), fadd2(p0[b], p1[b]));
            float l0, l1; upk(ss2, l0, l1);
            sm->zb2[bl][gate][lane] = (l0 + l1) + bs2;
        }
        barsync(barid);
        // phase D: cell2(s) + output(s) + xg
        if (own) {
            const int bo = gb + gate;
            float zi = sm->zb2[bo][0][lane], zf = sm->zb2[bo][1][lane];
            float zg = sm->zb2[bo][2][lane], zo = sm->zb2[bo][3][lane];
            c2 = fmaf(sigm(zf), c2, sigm(zi) * tanh_f(zg));
            float h2new = sigm(zo) * tanh_f(c2);
            sm->h2s[bo][lane] = h2new;
            float v = wlin * h2new;
            #pragma unroll
            for (int off = 16; off; off >>= 1)
                v += __shfl_xor_sync(0xffffffffu, v, off);
            if (lane == 0) {
                float o = v + blin;
                out_row[s] = o;
                sm->xg[bo] = o;
            }
        }
        barsync(barid);   // orders xg/h2s writes before next step's reads
    }
}

__global__ void __launch_bounds__(384, 1)
lstm_seq_kernel(const float* __restrict__ input,
                const float* __restrict__ W_ih1, const float* __restrict__ W_hh1,
                const float* __restrict__ b_ih1, const float* __restrict__ b_hh1,
                const float* __restrict__ W_ih2, const float* __restrict__ W_hh2,
                const float* __restrict__ b_ih2, const float* __restrict__ b_hh2,
                const float* __restrict__ W_lin, const float* __restrict__ b_lin,
                float* __restrict__ out)
{
    __shared__ __align__(16) SmemLayout sm;

    const int tid   = threadIdx.x;
    const int wid   = tid >> 5;
    const int lane  = tid & 31;
    const int group = wid >> 2;        // 0,1,2
    const int gate  = wid & 3;         // gate row group (i,f,g,o)
    const int row   = gate * Hh + lane;

    // Balanced batch partition: 136 CTAs x 7 + 12 CTAs x 6 = 1024.
    const int bid      = blockIdx.x;
    const int cta_base = (bid < 136) ? bid * 7 : 952 + (bid - 136) * 6;
    const int nb_cta   = (bid < 136) ? 7 : 6;

    // ---- register-resident weights, packed as consecutive-k f32x2 pairs ----
    u64 whh1[16], wih2[16], whh2[16];
    {
        const float2* W1  = reinterpret_cast<const float2*>(W_hh1);
        const float2* W2i = reinterpret_cast<const float2*>(W_ih2);
        const float2* W2h = reinterpret_cast<const float2*>(W_hh2);
        #pragma unroll
        for (int p = 0; p < 16; p++) {
            float2 a = __ldg(W1  + row * 16 + p); whh1[p] = pk2(a.x, a.y);
            float2 c = __ldg(W2i + row * 16 + p); wih2[p] = pk2(c.x, c.y);
            float2 d = __ldg(W2h + row * 16 + p); whh2[p] = pk2(d.x, d.y);
        }
    }
    const float wih1r = __ldg(W_ih1 + row);                      // [4H,1]
    const float bs1   = __ldg(b_ih1 + row) + __ldg(b_hh1 + row);
    const float bs2   = __ldg(b_ih2 + row) + __ldg(b_hh2 + row);
    const float wlin  = __ldg(W_lin + lane);
    const float blin  = __ldg(b_lin);

    // ---- stage input rows (warp w loads batch row w, coalesced) ----
    if (wid < nb_cta) {
        const float* src = input + (long)(cta_base + wid) * TIN;
        for (int k = lane; k < TIN; k += 32) sm.xs[wid][k] = src[k];
    }
    if (tid < MAXB * Hh) {
        (&sm.h1s[0][0])[tid] = 0.0f;
        (&sm.h2s[0][0])[tid] = 0.0f;
    }
    __syncthreads();   // one block-wide barrier before the group-local loops

    // Groups: g0 -> 3 batches at +0, g1 -> 2 at +3, g2 -> (nb_cta-5) at +5.
    const int gb    = (group == 0) ? 0 : (group == 1 ? 3 : 5);
    const int nbl   = (group == 0) ? 3 : (group == 1 ? 2 : nb_cta - 5);
    const int barid = group + 1;
    float* out_row  = (gate < nbl)
                    ? out + (long)(cta_base + gb + gate) * TOT
                    : out;   // unused (guarded by `own`), keep valid

    if (group == 0) {
        run_loop<3>(&sm, gb, barid, gate, lane, whh1, wih2, whh2,
                    wih1r, bs1, bs2, wlin, blin, out_row);
    } else if (group == 1) {
        run_loop<2>(&sm, gb, barid, gate, lane, whh1, wih2, whh2,
                    wih1r, bs1, bs2, wlin, blin, out_row);
    } else if (nbl == 2) {
        run_loop<2>(&sm, gb, barid, gate, lane, whh1, wih2, whh2,
                    wih1r, bs1, bs2, wlin, blin, out_row);
    } else {
        run_loop<1>(&sm, gb, barid, gate, lane, whh1, wih2, whh2,
                    wih1r, bs1, bs2, wlin, blin, out_row);
    }
}

extern "C" void kernel_launch(void* const* d_in, const int* in_sizes, int n_in,
                              void* d_out, int out_size)
{
    (void)in_sizes; (void)n_in; (void)out_size;
    const float* input = (const float*)d_in[0];
    const float* W_ih1 = (const float*)d_in[1];
    const float* W_hh1 = (const float*)d_in[2];
    const float* b_ih1 = (const float*)d_in[3];
    const float* b_hh1 = (const float*)d_in[4];
    const float* W_ih2 = (const float*)d_in[5];
    const float* W_hh2 = (const float*)d_in[6];
    const float* b_ih2 = (const float*)d_in[7];
    const float* b_hh2 = (const float*)d_in[8];
    const float* W_lin = (const float*)d_in[9];
    const float* b_lin = (const float*)d_in[10];
    // d_in[11] = future (fixed at 1000 by the problem definition)

    dim3 grid(148);    // 1 CTA per SM
    dim3 block(384);   // 3 gate-groups x 4 warps = 12 warps/SM
    lstm_seq_kernel<<<grid, block>>>(input, W_ih1, W_hh1, b_ih1, b_hh1,
                                     W_ih2, W_hh2, b_ih2, b_hh2,
                                     W_lin, b_lin, (float*)d_out);
}

// round 17
// speedup vs baseline: 1.2752x; 1.1284x over previous
#include <cuda_runtime.h>

#define Hh    32
#define TIN   999
#define TINP  1000   // padded stride so arrays after xs stay 16B-aligned
#define TOT   1999
#define MAXB  7      // max batches per CTA

typedef unsigned long long u64;

// ---- packed f32x2 helpers (Blackwell FFMA2/FADD2 path, PTX-only) ----
__device__ __forceinline__ u64 pk2(float a, float b) {
    u64 r; asm("mov.b64 %0, {%1, %2};" : "=l"(r) : "f"(a), "f"(b)); return r;
}
__device__ __forceinline__ void upk(u64 v, float& a, float& b) {
    asm("mov.b64 {%0, %1}, %2;" : "=f"(a), "=f"(b) : "l"(v));
}
__device__ __forceinline__ void ffma2(u64& d, u64 a, u64 b) {
    asm("fma.rn.f32x2 %0, %1, %2, %0;" : "+l"(d) : "l"(a), "l"(b));
}
__device__ __forceinline__ u64 fadd2(u64 a, u64 b) {
    u64 r; asm("add.rn.f32x2 %0, %1, %2;" : "=l"(r) : "l"(a), "l"(b)); return r;
}

// ---- precise fast activations: MUFU.EX2 / MUFU.RCP (~4e-7 rel err) ----
__device__ __forceinline__ float sigm(float x) {
    float t, r;
    asm("ex2.approx.f32 %0, %1;" : "=f"(t) : "f"(x * -1.4426950408889634f));
    asm("rcp.approx.f32 %0, %1;" : "=f"(r) : "f"(1.0f + t));
    return r;
}
__device__ __forceinline__ float tanh_f(float x) {
    float t, r;
    asm("ex2.approx.f32 %0, %1;" : "=f"(t) : "f"(x * -2.8853900817779268f));
    asm("rcp.approx.f32 %0, %1;" : "=f"(r) : "f"(1.0f + t));
    return fmaf(2.0f, r, -1.0f);   // tanh(x) = 2*sigmoid(2x) - 1
}

// group-local named barrier: 128 threads (4 warps) of one gate-group
__device__ __forceinline__ void barsync(int id) {
    asm volatile("bar.sync %0, 128;" :: "r"(id) : "memory");
}

struct SmemLayout {
    float xs[MAXB][TINP];       // staged input rows (padded stride)
    float h1s[MAXB][Hh];        // layer-1 hidden
    float h2s[MAXB][Hh];        // layer-2 hidden
    float zb1[MAXB][4][Hh];     // layer-1 gate scratch
    float zb2[MAXB][4][Hh];     // layer-2 gate scratch
};

template<int NBL>
__device__ __forceinline__ void run_loop(
    SmemLayout* sm, int gb, int barid, int gate, int lane,
    const u64* whh1, const u64* wih2, const u64* whh2,
    float wih1r, const float* wih1g, float bs1, float bs2,
    float wlin, float blin, float* out_row)
{
    float c1 = 0.0f, c2 = 0.0f;
    const bool own = (gate < NBL);   // warp-uniform

    // ---- prologue: A(0) (h1 = 0, so z1 = wih1*x0 + b), then cell1(0) ----
    #pragma unroll
    for (int b = 0; b < NBL; b++) {
        const int bl = gb + b;
        sm->zb1[bl][gate][lane] = fmaf(wih1r, sm->xs[bl][0], bs1);
    }
    barsync(barid);
    if (own) {
        const int bo = gb + gate;
        float zi = sm->zb1[bo][0][lane], zf = sm->zb1[bo][1][lane];
        float zg = sm->zb1[bo][2][lane], zo = sm->zb1[bo][3][lane];
        c1 = fmaf(sigm(zf), c1, sigm(zi) * tanh_f(zg));
        sm->h1s[bo][lane] = sigm(zo) * tanh_f(c1);
    }
    barsync(barid);

    // ============ teacher steady state: s = 0 .. TIN-2 (x from xs) =========
    // X(s): zb2(s) = Wih2@h1(s) + Whh2@h2(s-1) + b;
    //       zb1(s+1) = Whh1@h1(s) + wih1*x(s+1) + b.  h1(s) loaded once.
    // Y(s): cell2(s)->h2(s)+out(s); cell1(s+1)->h1(s+1). 2 barriers/step.
    for (int s = 0; s < TIN - 1; s++) {
        #pragma unroll
        for (int b = 0; b < NBL; b++) {
            const int bl = gb + b;
            u64 aA0 = 0ull, aA1 = 0ull, aC0 = 0ull, aC1 = 0ull;
            u64 aB0 = 0ull, aB1 = 0ull;
            const ulonglong2* hp1 =
                reinterpret_cast<const ulonglong2*>(sm->h1s[bl]);
            const ulonglong2* hp2 =
                reinterpret_cast<const ulonglong2*>(sm->h2s[bl]);
            #pragma unroll
            for (int p = 0; p < 8; p++) {
                ulonglong2 hv = hp1[p];            // h1(s): feeds A and C
                ffma2(aA0, hv.x, whh1[2 * p]);
                ffma2(aA1, hv.y, whh1[2 * p + 1]);
                ffma2(aC0, hv.x, wih2[2 * p]);
                ffma2(aC1, hv.y, wih2[2 * p + 1]);
                ulonglong2 wv = hp2[p];            // h2(s-1)
                ffma2(aB0, wv.x, whh2[2 * p]);
                ffma2(aB1, wv.y, whh2[2 * p + 1]);
            }
            {
                u64 aa = fadd2(aA0, aA1);
                float l0, l1; upk(aa, l0, l1);
                sm->zb1[bl][gate][lane] =
                    (l0 + l1) + fmaf(wih1r, sm->xs[bl][s + 1], bs1);
            }
            {
                u64 ss2 = fadd2(fadd2(aC0, aB0), fadd2(aC1, aB1));
                float l0, l1; upk(ss2, l0, l1);
                sm->zb2[bl][gate][lane] = (l0 + l1) + bs2;
            }
        }
        barsync(barid);
        if (own) {
            const int bo = gb + gate;
            {   // cell2(s) + output(s)
                float zi = sm->zb2[bo][0][lane], zf = sm->zb2[bo][1][lane];
                float zg = sm->zb2[bo][2][lane], zo = sm->zb2[bo][3][lane];
                c2 = fmaf(sigm(zf), c2, sigm(zi) * tanh_f(zg));
                float h2new = sigm(zo) * tanh_f(c2);
                sm->h2s[bo][lane] = h2new;
                float v = wlin * h2new;
                #pragma unroll
                for (int off = 16; off; off >>= 1)
                    v += __shfl_xor_sync(0xffffffffu, v, off);
                if (lane == 0) out_row[s] = v + blin;
            }
            {   // cell1(s+1)
                float zi = sm->zb1[bo][0][lane], zf = sm->zb1[bo][1][lane];
                float zg = sm->zb1[bo][2][lane], zo = sm->zb1[bo][3][lane];
                c1 = fmaf(sigm(zf), c1, sigm(zi) * tanh_f(zg));
                sm->h1s[bo][lane] = sigm(zo) * tanh_f(c1);
            }
        }
        barsync(barid);
    }

    // ===== unified generative-style loop: s = TIN-1 .. TOT-1 ==============
    // x(s+1) = o(s) is not known in X, so zb1 carries only the matvec part:
    //   X(s): zb2(s) as above; zb1p(s+1) = Whh1@h1(s) + bs1   (no x-term)
    //   Y(s): cell2(s)->h2(s); butterfly leaves o(s) in ALL lanes; out(s);
    //         cell1(s+1): z_g = zb1p[bo][g][lane] + wih1g[g]*o(s).
    // Feedback is register-local to the owning warp (no smem xg).
    for (int s = TIN - 1; s < TOT; s++) {
        #pragma unroll
        for (int b = 0; b < NBL; b++) {
            const int bl = gb + b;
            u64 aA0 = 0ull, aA1 = 0ull, aC0 = 0ull, aC1 = 0ull;
            u64 aB0 = 0ull, aB1 = 0ull;
            const ulonglong2* hp1 =
                reinterpret_cast<const ulonglong2*>(sm->h1s[bl]);
            const ulonglong2* hp2 =
                reinterpret_cast<const ulonglong2*>(sm->h2s[bl]);
            #pragma unroll
            for (int p = 0; p < 8; p++) {
                ulonglong2 hv = hp1[p];            // h1(s): feeds A' and C
                ffma2(aA0, hv.x, whh1[2 * p]);
                ffma2(aA1, hv.y, whh1[2 * p + 1]);
                ffma2(aC0, hv.x, wih2[2 * p]);
                ffma2(aC1, hv.y, wih2[2 * p + 1]);
                ulonglong2 wv = hp2[p];            // h2(s-1)
                ffma2(aB0, wv.x, whh2[2 * p]);
                ffma2(aB1, wv.y, whh2[2 * p + 1]);
            }
            {
                u64 aa = fadd2(aA0, aA1);
                float l0, l1; upk(aa, l0, l1);
                sm->zb1[bl][gate][lane] = (l0 + l1) + bs1;   // partial: no x
            }
            {
                u64 ss2 = fadd2(fadd2(aC0, aB0), fadd2(aC1, aB1));
                float l0, l1; upk(ss2, l0, l1);
                sm->zb2[bl][gate][lane] = (l0 + l1) + bs2;
            }
        }
        barsync(barid);
        if (own) {
            const int bo = gb + gate;
            float o;
            {   // cell2(s) + output(s); butterfly -> o in all lanes
                float zi = sm->zb2[bo][0][lane], zf = sm->zb2[bo][1][lane];
                float zg = sm->zb2[bo][2][lane], zo = sm->zb2[bo][3][lane];
                c2 = fmaf(sigm(zf), c2, sigm(zi) * tanh_f(zg));
                float h2new = sigm(zo) * tanh_f(c2);
                sm->h2s[bo][lane] = h2new;
                float v = wlin * h2new;
                #pragma unroll
                for (int off = 16; off; off >>= 1)
                    v += __shfl_xor_sync(0xffffffffu, v, off);
                o = v + blin;
                if (lane == 0) out_row[s] = o;
            }
            {   // cell1(s+1): add the deferred rank-1 x-term
                float zi = fmaf(wih1g[0], o, sm->zb1[bo][0][lane]);
                float zf = fmaf(wih1g[1], o, sm->zb1[bo][1][lane]);
                float zg = fmaf(wih1g[2], o, sm->zb1[bo][2][lane]);
                float zo = fmaf(wih1g[3], o, sm->zb1[bo][3][lane]);
                c1 = fmaf(sigm(zf), c1, sigm(zi) * tanh_f(zg));
                sm->h1s[bo][lane] = sigm(zo) * tanh_f(c1);
            }
        }
        barsync(barid);
    }
}

__global__ void __launch_bounds__(384, 1)
lstm_seq_kernel(const float* __restrict__ input,
                const float* __restrict__ W_ih1, const float* __restrict__ W_hh1,
                const float* __restrict__ b_ih1, const float* __restrict__ b_hh1,
                const float* __restrict__ W_ih2, const float* __restrict__ W_hh2,
                const float* __restrict__ b_ih2, const float* __restrict__ b_hh2,
                const float* __restrict__ W_lin, const float* __restrict__ b_lin,
                float* __restrict__ out)
{
    __shared__ __align__(16) SmemLayout sm;

    const int tid   = threadIdx.x;
    const int wid   = tid >> 5;
    const int lane  = tid & 31;
    const int group = wid >> 2;        // 0,1,2
    const int gate  = wid & 3;         // gate row group (i,f,g,o)
    const int row   = gate * Hh + lane;

    // Balanced batch partition: 136 CTAs x 7 + 12 CTAs x 6 = 1024.
    const int bid      = blockIdx.x;
    const int cta_base = (bid < 136) ? bid * 7 : 952 + (bid - 136) * 6;
    const int nb_cta   = (bid < 136) ? 7 : 6;

    // ---- register-resident weights, packed as consecutive-k f32x2 pairs ----
    u64 whh1[16], wih2[16], whh2[16];
    {
        const float2* W1  = reinterpret_cast<const float2*>(W_hh1);
        const float2* W2i = reinterpret_cast<const float2*>(W_ih2);
        const float2* W2h = reinterpret_cast<const float2*>(W_hh2);
        #pragma unroll
        for (int p = 0; p < 16; p++) {
            float2 a = __ldg(W1  + row * 16 + p); whh1[p] = pk2(a.x, a.y);
            float2 c = __ldg(W2i + row * 16 + p); wih2[p] = pk2(c.x, c.y);
            float2 d = __ldg(W2h + row * 16 + p); whh2[p] = pk2(d.x, d.y);
        }
    }
    const float wih1r = __ldg(W_ih1 + row);                      // own gate row
    float wih1g[4];                                              // all 4 gate rows
    #pragma unroll
    for (int g = 0; g < 4; g++) wih1g[g] = __ldg(W_ih1 + g * Hh + lane);
    const float bs1   = __ldg(b_ih1 + row) + __ldg(b_hh1 + row);
    const float bs2   = __ldg(b_ih2 + row) + __ldg(b_hh2 + row);
    const float wlin  = __ldg(W_lin + lane);
    const float blin  = __ldg(b_lin);

    // ---- stage input rows (warp w loads batch row w, coalesced) ----
    if (wid < nb_cta) {
        const float* src = input + (long)(cta_base + wid) * TIN;
        for (int k = lane; k < TIN; k += 32) sm.xs[wid][k] = src[k];
    }
    if (tid < MAXB * Hh) {
        (&sm.h1s[0][0])[tid] = 0.0f;
        (&sm.h2s[0][0])[tid] = 0.0f;
    }
    __syncthreads();   // one block-wide barrier before the group-local loops

    // Groups: g0 -> 3 batches at +0, g1 -> 2 at +3, g2 -> (nb_cta-5) at +5.
    const int gb    = (group == 0) ? 0 : (group == 1 ? 3 : 5);
    const int nbl   = (group == 0) ? 3 : (group == 1 ? 2 : nb_cta - 5);
    const int barid = group + 1;
    float* out_row  = (gate < nbl)
                    ? out + (long)(cta_base + gb + gate) * TOT
                    : out;   // unused (guarded by `own`), keep valid

    if (group == 0) {
        run_loop<3>(&sm, gb, barid, gate, lane, whh1, wih2, whh2,
                    wih1r, wih1g, bs1, bs2, wlin, blin, out_row);
    } else if (group == 1) {
        run_loop<2>(&sm, gb, barid, gate, lane, whh1, wih2, whh2,
                    wih1r, wih1g, bs1, bs2, wlin, blin, out_row);
    } else if (nbl == 2) {
        run_loop<2>(&sm, gb, barid, gate, lane, whh1, wih2, whh2,
                    wih1r, wih1g, bs1, bs2, wlin, blin, out_row);
    } else {
        run_loop<1>(&sm, gb, barid, gate, lane, whh1, wih2, whh2,
                    wih1r, wih1g, bs1, bs2, wlin, blin, out_row);
    }
}

extern "C" void kernel_launch(void* const* d_in, const int* in_sizes, int n_in,
                              void* d_out, int out_size)
{
    (void)in_sizes; (void)n_in; (void)out_size;
    const float* input = (const float*)d_in[0];
    const float* W_ih1 = (const float*)d_in[1];
    const float* W_hh1 = (const float*)d_in[2];
    const float* b_ih1 = (const float*)d_in[3];
    const float* b_hh1 = (const float*)d_in[4];
    const float* W_ih2 = (const float*)d_in[5];
    const float* W_hh2 = (const float*)d_in[6];
    const float* b_ih2 = (const float*)d_in[7];
    const float* b_hh2 = (const float*)d_in[8];
    const float* W_lin = (const float*)d_in[9];
    const float* b_lin = (const float*)d_in[10];
    // d_in[11] = future (fixed at 1000 by the problem definition)

    dim3 grid(148);    // 1 CTA per SM
    dim3 block(384);   // 3 gate-groups x 4 warps = 12 warps/SM
    lstm_seq_kernel<<<grid, block>>>(input, W_ih1, W_hh1, b_ih1, b_hh1,
                                     W_ih2, W_hh2, b_ih2, b_hh2,
                                     W_lin, b_lin, (float*)d_out);
}